// round 6
// baseline (speedup 1.0000x reference)
#include <cuda_runtime.h>

#define D_DIM   512
#define H1_DIM  128
#define H2_DIM  64
#define B_DIM   2048
#define N_NODES 20000
#define N_DRUG  2000

typedef unsigned long long ull;
typedef ulonglong2 ull2;

__device__ __forceinline__ ull pack2s(float x) {            // {x, x}
    ull r; asm("mov.b64 %0, {%1, %1};" : "=l"(r) : "f"(x)); return r;
}
__device__ __forceinline__ void ffma2(ull& d, ull a, ull b) { // d += a*b (2-lane)
    asm("fma.rn.f32x2 %0, %1, %2, %3;" : "=l"(d) : "l"(a), "l"(b), "l"(d));
}
__device__ __forceinline__ float2 unpk(ull v) {
    float2 f; asm("mov.b64 {%0, %1}, %2;" : "=f"(f.x), "=f"(f.y) : "l"(v)); return f;
}

// Scratch: layer-1 partial products
__device__ float g_Ptop[N_DRUG  * H1_DIM];   // embed[:2000]  @ W1[0:512]
__device__ float g_Pbot[N_NODES * H1_DIM];   // embed[:20000] @ W1[512:1024]

// ---------------------------------------------------------------------------
// Kernel 1: P[r][o] = sum_d embed[r][d] * W1[woff+d][o]
// 64x128 tile, BK=16, 256 threads. Micro-tile 16 rows x 2 cols:
//   row-pairs loaded NATIVELY packed (ulonglong2 from k-major As) -> 0 movs,
//   w broadcast: 2 packs (4 movs) per k. Double-buffered smem + reg prefetch.
// ---------------------------------------------------------------------------
#define AS_STRIDE 68

__global__ void __launch_bounds__(256, 3) gemm1_kernel(const float* __restrict__ embed,
                                                       const float* __restrict__ W1) {
    const int NBOT = (N_NODES + 63) / 64;   // 313
    int bx = blockIdx.x;
    int woff, M;
    float* P;
    if (bx < NBOT) { woff = D_DIM; M = N_NODES; P = g_Pbot; }
    else           { bx -= NBOT; woff = 0; M = N_DRUG; P = g_Ptop; }
    const int row0 = bx * 64;

    __shared__ float As[2][16 * AS_STRIDE];   // k-major [16][64(+pad)]
    __shared__ float Bs[2][16 * 128];         // k-major [16][128]

    const int tid = threadIdx.x;
    const int tx = tid & 63;        // col pair: cols 2tx, 2tx+1
    const int ty = tid >> 6;        // row group: rows 16ty .. 16ty+15 (warp-uniform)

    ull acc[8][2];                  // [row-pair][col]
#pragma unroll
    for (int i = 0; i < 8; i++) { acc[i][0] = 0ull; acc[i][1] = 0ull; }

    // staging assignment
    const int ar = tid >> 2;              // 0..63
    const int ac = (tid & 3) << 2;        // 0,4,8,12
    const int agr = min(row0 + ar, M - 1);
    const float* aptr  = embed + agr * D_DIM + ac;
    const int sty = tid >> 5;             // 0..7 (B staging row)
    const int scc = (tid & 31) << 2;      // 0..124
    const float* bptr0 = W1 + (woff + sty)     * H1_DIM + scc;
    const float* bptr1 = W1 + (woff + sty + 8) * H1_DIM + scc;

    // prologue: fetch tile 0 into buf 0
    float4 a_reg  = *(const float4*)(aptr);
    float4 b_reg0 = *(const float4*)(bptr0);
    float4 b_reg1 = *(const float4*)(bptr1);
    As[0][(ac + 0) * AS_STRIDE + ar] = a_reg.x;
    As[0][(ac + 1) * AS_STRIDE + ar] = a_reg.y;
    As[0][(ac + 2) * AS_STRIDE + ar] = a_reg.z;
    As[0][(ac + 3) * AS_STRIDE + ar] = a_reg.w;
    *(float4*)&Bs[0][sty * 128 + scc]       = b_reg0;
    *(float4*)&Bs[0][(sty + 8) * 128 + scc] = b_reg1;
    __syncthreads();

#pragma unroll 2
    for (int t = 0; t < 32; t++) {
        const int cur = t & 1;
        const int nxt = cur ^ 1;
        if (t < 31) {   // register prefetch of next tile (overlaps compute)
            int k0 = (t + 1) * 16;
            a_reg  = *(const float4*)(aptr + k0);
            b_reg0 = *(const float4*)(bptr0 + k0 * H1_DIM);
            b_reg1 = *(const float4*)(bptr1 + k0 * H1_DIM);
        }
#pragma unroll
        for (int k = 0; k < 16; k++) {
            const float* arow = &As[cur][k * AS_STRIDE + ty * 16];
            const ull2 a01 = *(const ull2*)(arow + 0);    // rows {0,1},{2,3}
            const ull2 a23 = *(const ull2*)(arow + 4);    // rows {4,5},{6,7}
            const ull2 a45 = *(const ull2*)(arow + 8);
            const ull2 a67 = *(const ull2*)(arow + 12);
            const float2 w = *(const float2*)&Bs[cur][k * 128 + (tx << 1)];
            const ull wx = pack2s(w.x);
            const ull wy = pack2s(w.y);
            ffma2(acc[0][0], a01.x, wx); ffma2(acc[0][1], a01.x, wy);
            ffma2(acc[1][0], a01.y, wx); ffma2(acc[1][1], a01.y, wy);
            ffma2(acc[2][0], a23.x, wx); ffma2(acc[2][1], a23.x, wy);
            ffma2(acc[3][0], a23.y, wx); ffma2(acc[3][1], a23.y, wy);
            ffma2(acc[4][0], a45.x, wx); ffma2(acc[4][1], a45.x, wy);
            ffma2(acc[5][0], a45.y, wx); ffma2(acc[5][1], a45.y, wy);
            ffma2(acc[6][0], a67.x, wx); ffma2(acc[6][1], a67.x, wy);
            ffma2(acc[7][0], a67.y, wx); ffma2(acc[7][1], a67.y, wy);
        }
        if (t < 31) {
            As[nxt][(ac + 0) * AS_STRIDE + ar] = a_reg.x;
            As[nxt][(ac + 1) * AS_STRIDE + ar] = a_reg.y;
            As[nxt][(ac + 2) * AS_STRIDE + ar] = a_reg.z;
            As[nxt][(ac + 3) * AS_STRIDE + ar] = a_reg.w;
            *(float4*)&Bs[nxt][sty * 128 + scc]       = b_reg0;
            *(float4*)&Bs[nxt][(sty + 8) * 128 + scc] = b_reg1;
            __syncthreads();
        }
    }

    // epilogue: acc[p][c] = {row 2p, row 2p+1} for col c
#pragma unroll
    for (int p = 0; p < 8; p++) {
        float2 c0 = unpk(acc[p][0]);   // (r_even, r_odd) col 2tx
        float2 c1 = unpk(acc[p][1]);   // (r_even, r_odd) col 2tx+1
        int r0 = row0 + ty * 16 + 2 * p;
        if (r0 < M)     *(float2*)&P[r0 * H1_DIM + (tx << 1)]       = make_float2(c0.x, c1.x);
        if (r0 + 1 < M) *(float2*)&P[(r0 + 1) * H1_DIM + (tx << 1)] = make_float2(c0.y, c1.y);
    }
}

// ---------------------------------------------------------------------------
// Kernel 2: 128 samples/block, 256 threads.
// X1 stored TRANSPOSED: X1T[k][sample] so sample-pairs load natively packed.
// Micro-tile 16 samples x 2 cols; 2 w-broadcast packs per k.
// ---------------------------------------------------------------------------
#define NSAMP 128
#define X1T_STRIDE 132   // 132 % 4 == 0 (float4 align), 2-way STS conflict in phase 1
#define SMEM2_BYTES ((H1_DIM * X1T_STRIDE + 128 * 64 + 128 + 64 + 64 + 3 * NSAMP) * 4)

__global__ void __launch_bounds__(256) mlp2_kernel(
    const int* __restrict__ h, const int* __restrict__ t, const int* __restrict__ ns,
    const float* __restrict__ b1, const float* __restrict__ W2,
    const float* __restrict__ b2, const float* __restrict__ W3,
    const float* __restrict__ b3, float* __restrict__ out)
{
    extern __shared__ float smem[];
    float* X1T = smem;                        // [128 k][132]
    float* W2s = X1T + H1_DIM * X1T_STRIDE;   // [128][64] k-major
    float* b1s = W2s + 128 * 64;              // [128]
    float* b2s = b1s + 128;                   // [64]
    float* W3s = b2s + 64;                    // [64]
    int* sTop = (int*)(W3s + 64);             // [128]
    int* sBot = sTop + NSAMP;                 // [128]
    int* sOut = sBot + NSAMP;                 // [128]

    const int tid = threadIdx.x;

    // ---- phase 0: decode samples + stage small tensors ----
    if (tid < NSAMP) {
        int S = blockIdx.x * NSAMP + tid;
        int b = S / 65;
        int r = S - b * 65;
        int itop, jbot, oaddr;
        if (r == 64)      { itop = h[b];           jbot = t[b];           oaddr = b; }
        else if (r < 32)  { itop = h[b];           jbot = ns[b * 64 + r]; oaddr = B_DIM + b * 64 + r; }
        else              { itop = ns[b * 64 + r]; jbot = t[b];           oaddr = B_DIM + b * 64 + r; }
        sTop[tid] = itop; sBot[tid] = jbot; sOut[tid] = oaddr;
    }
#pragma unroll
    for (int i = tid; i < 2048; i += 256)   // W2: 2048 float4
        ((float4*)W2s)[i] = ((const float4*)W2)[i];
    if (tid < 128) b1s[tid] = b1[tid];
    if (tid < 64) { b2s[tid] = b2[tid]; W3s[tid] = W3[tid]; }
    __syncthreads();

    // ---- phase 1: X1T[k][s] = relu(Ptop[i][k] + Pbot[j][k] + b1[k]) ----
    // Lane map: 8 samples x 4-k chunks per warp -> 2-way STS conflicts only.
    {
        const int lane = tid & 31;
        const int wid = tid >> 5;
        const int sl = lane >> 2;          // 0..7 sample within warp group
        const int k0 = (lane & 3) << 2;    // 0,4,8,12
#pragma unroll
        for (int sg = 0; sg < 2; sg++) {
            int s = sg * 64 + wid * 8 + sl;
            const float* pt = g_Ptop + sTop[s] * H1_DIM;
            const float* pb = g_Pbot + sBot[s] * H1_DIM;
#pragma unroll
            for (int kb = 0; kb < H1_DIM; kb += 16) {
                int k = kb + k0;
                float4 pa = *(const float4*)&pt[k];
                float4 pv = *(const float4*)&pb[k];
                float4 vb = *(const float4*)&b1s[k];
                X1T[(k + 0) * X1T_STRIDE + s] = fmaxf(pa.x + pv.x + vb.x, 0.f);
                X1T[(k + 1) * X1T_STRIDE + s] = fmaxf(pa.y + pv.y + vb.y, 0.f);
                X1T[(k + 2) * X1T_STRIDE + s] = fmaxf(pa.z + pv.z + vb.z, 0.f);
                X1T[(k + 3) * X1T_STRIDE + s] = fmaxf(pa.w + pv.w + vb.w, 0.f);
            }
        }
    }
    __syncthreads();

    // ---- phase 2: [128s x 128k] @ [128k x 64c], native sample-pairs ----
    const int tx = tid & 31;   // col pair: cols 2tx, 2tx+1
    const int ty = tid >> 5;   // samples 16ty .. 16ty+15 (warp-uniform)

    ull acc[8][2];             // [sample-pair][col]
#pragma unroll
    for (int i = 0; i < 8; i++) { acc[i][0] = 0ull; acc[i][1] = 0ull; }

#pragma unroll 4
    for (int k = 0; k < H1_DIM; k++) {
        const float* xrow = &X1T[k * X1T_STRIDE + ty * 16];
        const ull2 a01 = *(const ull2*)(xrow + 0);
        const ull2 a23 = *(const ull2*)(xrow + 4);
        const ull2 a45 = *(const ull2*)(xrow + 8);
        const ull2 a67 = *(const ull2*)(xrow + 12);
        const float2 w = *(const float2*)&W2s[k * H2_DIM + (tx << 1)];
        const ull wx = pack2s(w.x);
        const ull wy = pack2s(w.y);
        ffma2(acc[0][0], a01.x, wx); ffma2(acc[0][1], a01.x, wy);
        ffma2(acc[1][0], a01.y, wx); ffma2(acc[1][1], a01.y, wy);
        ffma2(acc[2][0], a23.x, wx); ffma2(acc[2][1], a23.x, wy);
        ffma2(acc[3][0], a23.y, wx); ffma2(acc[3][1], a23.y, wy);
        ffma2(acc[4][0], a45.x, wx); ffma2(acc[4][1], a45.x, wy);
        ffma2(acc[5][0], a45.y, wx); ffma2(acc[5][1], a45.y, wy);
        ffma2(acc[6][0], a67.x, wx); ffma2(acc[6][1], a67.x, wy);
        ffma2(acc[7][0], a67.y, wx); ffma2(acc[7][1], a67.y, wy);
    }

    // ---- phase 3: layer 3 + full-warp reduction (64 cols across 32 lanes) ----
    const float2 b2r = *(const float2*)&b2s[tx << 1];
    const float2 w3r = *(const float2*)&W3s[tx << 1];
    const float b3v = b3[0];

#pragma unroll
    for (int p = 0; p < 8; p++) {
        float2 c0 = unpk(acc[p][0]);   // (s_even, s_odd) col 2tx
        float2 c1 = unpk(acc[p][1]);   // (s_even, s_odd) col 2tx+1
        float p0 = fmaxf(c0.x + b2r.x, 0.f) * w3r.x + fmaxf(c1.x + b2r.y, 0.f) * w3r.y;
        float p1 = fmaxf(c0.y + b2r.x, 0.f) * w3r.x + fmaxf(c1.y + b2r.y, 0.f) * w3r.y;
#pragma unroll
        for (int m = 16; m > 0; m >>= 1) {
            p0 += __shfl_xor_sync(0xffffffffu, p0, m);
            p1 += __shfl_xor_sync(0xffffffffu, p1, m);
        }
        if (tx == 0) {
            int s0 = ty * 16 + 2 * p;
            out[sOut[s0]]     = p0 + b3v;
            out[sOut[s0 + 1]] = p1 + b3v;
        }
    }
}

// ---------------------------------------------------------------------------
extern "C" void kernel_launch(void* const* d_in, const int* in_sizes, int n_in,
                              void* d_out, int out_size) {
    const float* embed = (const float*)d_in[0];
    const float* W1    = (const float*)d_in[1];
    const float* b1    = (const float*)d_in[2];
    const float* W2    = (const float*)d_in[3];
    const float* b2    = (const float*)d_in[4];
    const float* W3    = (const float*)d_in[5];
    const float* b3    = (const float*)d_in[6];
    const int*   h     = (const int*)d_in[7];
    const int*   t     = (const int*)d_in[8];
    const int*   ns    = (const int*)d_in[9];
    float* out = (float*)d_out;

    const int NBOT = (N_NODES + 63) / 64;   // 313
    const int NTOP = (N_DRUG  + 63) / 64;   // 32
    gemm1_kernel<<<NBOT + NTOP, 256>>>(embed, W1);

    cudaFuncSetAttribute(mlp2_kernel, cudaFuncAttributeMaxDynamicSharedMemorySize,
                         SMEM2_BYTES);
    mlp2_kernel<<<(B_DIM * 65) / NSAMP, 256, SMEM2_BYTES>>>(h, t, ns, b1, W2, b2, W3, b3, out);
}

// round 8
// speedup vs baseline: 1.2533x; 1.2533x over previous
#include <cuda_runtime.h>
#include <cuda_bf16.h>

#define D_DIM   512
#define H1_DIM  128
#define H2_DIM  64
#define B_DIM   2048
#define N_NODES 20000
#define N_DRUG  2000

typedef unsigned long long ull;

__device__ __forceinline__ ull pack2s(float x) {            // {x, x}
    ull r; asm("mov.b64 %0, {%1, %1};" : "=l"(r) : "f"(x)); return r;
}
__device__ __forceinline__ void ffma2(ull& d, ull a, ull b) { // d += a*b (2-lane)
    asm("fma.rn.f32x2 %0, %1, %2, %3;" : "=l"(d) : "l"(a), "l"(b), "l"(d));
}
__device__ __forceinline__ float2 unpk(ull v) {
    float2 f; asm("mov.b64 {%0, %1}, %2;" : "=f"(f.x), "=f"(f.y) : "l"(v)); return f;
}
__device__ __forceinline__ unsigned smem_u32(const void* p) {
    unsigned a;
    asm("{ .reg .u64 t; cvta.to.shared.u64 t, %1; cvt.u32.u64 %0, t; }" : "=r"(a) : "l"(p));
    return a;
}

#define SW128(o) ((o) ^ ((((o) >> 3) & 0x70)))

// Scratch
__device__ float g_Ptop[N_DRUG  * H1_DIM];       // embed[:2000]  @ W1[0:512]
__device__ float g_Pbot[N_NODES * H1_DIM];       // embed[:20000] @ W1[512:1024]
__device__ __nv_bfloat16 g_Wthi[H1_DIM * 1024];  // W1^T hi  [n][k]
__device__ __nv_bfloat16 g_Wtlo[H1_DIM * 1024];  // W1^T lo  [n][k]

// ---------------------------------------------------------------------------
// Kernel 0: transpose + split W1 (fp32 [1024][128]) -> bf16 hi/lo [128][1024]
// ---------------------------------------------------------------------------
__global__ void convert_w1_kernel(const float* __restrict__ W1) {
    int n = blockIdx.x;                       // 0..127
    for (int k = threadIdx.x; k < 1024; k += 256) {
        float x = W1[k * H1_DIM + n];
        __nv_bfloat16 h = __float2bfloat16(x);
        float hf = __bfloat162float(h);
        g_Wthi[n * 1024 + k] = h;
        g_Wtlo[n * 1024 + k] = __float2bfloat16(x - hf);
    }
}

// ---------------------------------------------------------------------------
// Kernel 1: HMMA (mma.sync bf16, fp32 acc) with fp32-split 3-term emulation.
// Per CTA: 128x128 tile, 8 warps x (64x32), K in 8 chunks of 64.
// Smem: 4 x [128][64] bf16 SW128 tiles (Ahi/Alo/Bhi/Blo) = 64KB.
// ---------------------------------------------------------------------------
#define NBOT_TC 157   // ceil(20000/128)
#define NTOP_TC 16    // ceil(2000/128)

#define SM_AHI 0
#define SM_ALO 16384
#define SM_BHI 32768
#define SM_BLO 49152
#define G1_SMEM 65536

__device__ __forceinline__ void ldm_x4(unsigned addr, unsigned& r0, unsigned& r1,
                                       unsigned& r2, unsigned& r3) {
    asm volatile("ldmatrix.sync.aligned.m8n8.x4.shared.b16 {%0,%1,%2,%3}, [%4];"
                 : "=r"(r0), "=r"(r1), "=r"(r2), "=r"(r3) : "r"(addr));
}
__device__ __forceinline__ void mma_bf16(float* c, unsigned a0, unsigned a1,
                                         unsigned a2, unsigned a3,
                                         unsigned b0, unsigned b1) {
    asm volatile("mma.sync.aligned.m16n8k16.row.col.f32.bf16.bf16.f32 "
                 "{%0,%1,%2,%3}, {%4,%5,%6,%7}, {%8,%9}, {%0,%1,%2,%3};"
                 : "+f"(c[0]), "+f"(c[1]), "+f"(c[2]), "+f"(c[3])
                 : "r"(a0), "r"(a1), "r"(a2), "r"(a3), "r"(b0), "r"(b1));
}
// A fragment lane address: rows m0+ (lane&15), col16 = k0/8 + lane/16
__device__ __forceinline__ unsigned amat_addr(unsigned base, int m0, int k0, int lane) {
    unsigned off = (unsigned)((m0 + (lane & 15)) * 128 + ((k0 >> 3) + (lane >> 4)) * 16);
    return base + SW128(off);
}
// B fragment lane address: rows n0 + (lane&7) + 8*(lane/16), col16 = k0/8 + (lane>>3 & 1)
__device__ __forceinline__ unsigned bmat_addr(unsigned base, int n0, int k0, int lane) {
    unsigned off = (unsigned)((n0 + (lane & 7) + ((lane >> 4) << 3)) * 128
                            + ((k0 >> 3) + ((lane >> 3) & 1)) * 16);
    return base + SW128(off);
}

__global__ void __launch_bounds__(256) gemm1_mma_kernel(const float* __restrict__ embed) {
    extern __shared__ char sm[];
    const unsigned sb = smem_u32(sm);
    const int tid = threadIdx.x;
    const int wid = tid >> 5;
    const int lane = tid & 31;

    int bx = blockIdx.x;
    int woff, M, row0;
    float* P;
    if (bx < NBOT_TC) { woff = D_DIM; M = N_NODES; P = g_Pbot; row0 = bx * 128; }
    else { bx -= NBOT_TC; woff = 0; M = N_DRUG; P = g_Ptop; row0 = bx * 128; }
    const int rmax = M - 1;

    const int wr = wid >> 2;       // 0..1 -> rows 64*wr
    const int wc = wid & 3;        // 0..3 -> cols 32*wc
    const int nb = wc * 32;

    float acc[4][4][4];
#pragma unroll
    for (int i = 0; i < 4; i++)
#pragma unroll
        for (int j = 0; j < 4; j++)
#pragma unroll
            for (int q = 0; q < 4; q++) acc[i][j][q] = 0.f;

    // staging assignment: kq = 4-element k group, rr = row within 16-row pass
    const int kq = tid & 15;
    const int rr = tid >> 4;

    for (int c = 0; c < 8; c++) {
        const int kb = c * 64;
        // ---- stage A (fp32 -> bf16 hi/lo) and B (pre-split copy), SW128 ----
#pragma unroll
        for (int p = 0; p < 8; p++) {
            int row = p * 16 + rr;
            int rg = min(row0 + row, rmax);
            float4 v = *(const float4*)&embed[(size_t)rg * D_DIM + kb + kq * 4];
            // pack hi pairs (cvt.rn.bf16x2.f32 packs {hi,lo args} -> (y,x) order)
            unsigned hi01, hi23;
            asm("cvt.rn.bf16x2.f32 %0, %1, %2;" : "=r"(hi01) : "f"(v.y), "f"(v.x));
            asm("cvt.rn.bf16x2.f32 %0, %1, %2;" : "=r"(hi23) : "f"(v.w), "f"(v.z));
            // hi as fp32 = bf16 bits << 16
            float h0 = __uint_as_float(hi01 << 16);
            float h1 = __uint_as_float(hi01 & 0xffff0000u);
            float h2 = __uint_as_float(hi23 << 16);
            float h3 = __uint_as_float(hi23 & 0xffff0000u);
            unsigned lo01, lo23;
            asm("cvt.rn.bf16x2.f32 %0, %1, %2;" : "=r"(lo01) : "f"(v.y - h1), "f"(v.x - h0));
            asm("cvt.rn.bf16x2.f32 %0, %1, %2;" : "=r"(lo23) : "f"(v.w - h3), "f"(v.z - h2));
            unsigned off = SW128((unsigned)(row * 128 + kq * 8));
            *(uint2*)(sm + SM_AHI + off) = make_uint2(hi01, hi23);
            *(uint2*)(sm + SM_ALO + off) = make_uint2(lo01, lo23);
            // B: n == row
            *(uint2*)(sm + SM_BHI + off) = *(const uint2*)&g_Wthi[row * 1024 + woff + kb + kq * 4];
            *(uint2*)(sm + SM_BLO + off) = *(const uint2*)&g_Wtlo[row * 1024 + woff + kb + kq * 4];
        }
        __syncthreads();

        // ---- compute: 4 k16 steps ----
#pragma unroll
        for (int ks = 0; ks < 4; ks++) {
            const int k0 = ks * 16;
            unsigned bh[4][2], bl[4][2], t0, t1, t2, t3;
            ldm_x4(bmat_addr(sb + SM_BHI, nb,      k0, lane), t0, t1, t2, t3);
            bh[0][0] = t0; bh[0][1] = t1; bh[1][0] = t2; bh[1][1] = t3;
            ldm_x4(bmat_addr(sb + SM_BHI, nb + 16, k0, lane), t0, t1, t2, t3);
            bh[2][0] = t0; bh[2][1] = t1; bh[3][0] = t2; bh[3][1] = t3;
            ldm_x4(bmat_addr(sb + SM_BLO, nb,      k0, lane), t0, t1, t2, t3);
            bl[0][0] = t0; bl[0][1] = t1; bl[1][0] = t2; bl[1][1] = t3;
            ldm_x4(bmat_addr(sb + SM_BLO, nb + 16, k0, lane), t0, t1, t2, t3);
            bl[2][0] = t0; bl[2][1] = t1; bl[3][0] = t2; bl[3][1] = t3;
#pragma unroll
            for (int mf = 0; mf < 4; mf++) {
                const int m0 = wr * 64 + mf * 16;
                unsigned ah0, ah1, ah2, ah3, al0, al1, al2, al3;
                ldm_x4(amat_addr(sb + SM_AHI, m0, k0, lane), ah0, ah1, ah2, ah3);
                ldm_x4(amat_addr(sb + SM_ALO, m0, k0, lane), al0, al1, al2, al3);
#pragma unroll
                for (int nf = 0; nf < 4; nf++) {
                    mma_bf16(acc[mf][nf], ah0, ah1, ah2, ah3, bh[nf][0], bh[nf][1]);
                    mma_bf16(acc[mf][nf], ah0, ah1, ah2, ah3, bl[nf][0], bl[nf][1]);
                    mma_bf16(acc[mf][nf], al0, al1, al2, al3, bh[nf][0], bh[nf][1]);
                }
            }
        }
        __syncthreads();
    }

    // ---- epilogue: fragment layout c0,c1 = (m = lane/4, n = 2*(lane%4)+{0,1}),
    //                c2,c3 same at m+8 ----
#pragma unroll
    for (int mf = 0; mf < 4; mf++) {
#pragma unroll
        for (int nf = 0; nf < 4; nf++) {
            int r = row0 + wr * 64 + mf * 16 + (lane >> 2);
            int col = nb + nf * 8 + 2 * (lane & 3);
            if (r < M)
                *(float2*)&P[(size_t)r * H1_DIM + col] =
                    make_float2(acc[mf][nf][0], acc[mf][nf][1]);
            if (r + 8 < M)
                *(float2*)&P[(size_t)(r + 8) * H1_DIM + col] =
                    make_float2(acc[mf][nf][2], acc[mf][nf][3]);
        }
    }
}

// ---------------------------------------------------------------------------
// Kernel 2 (R2 design, measured 57.4us): 128 samples/block, 8x4 FFMA2 tile.
// ---------------------------------------------------------------------------
#define NSAMP 128
#define X1_STRIDE 132
#define SMEM2_BYTES ((NSAMP * X1_STRIDE + 128 * 64 + 128 + 64 + 64) * 4 + 3 * NSAMP * 4)

__global__ void __launch_bounds__(256) mlp2_kernel(
    const int* __restrict__ h, const int* __restrict__ t, const int* __restrict__ ns,
    const float* __restrict__ b1, const float* __restrict__ W2,
    const float* __restrict__ b2, const float* __restrict__ W3,
    const float* __restrict__ b3, float* __restrict__ out)
{
    extern __shared__ float smem[];
    float* X1  = smem;                       // [128][132]
    float* W2s = X1 + NSAMP * X1_STRIDE;     // [128][64] k-major
    float* b1s = W2s + 128 * 64;             // [128]
    float* b2s = b1s + 128;                  // [64]
    float* W3s = b2s + 64;                   // [64]
    int* sTop = (int*)(W3s + 64);            // [128]
    int* sBot = sTop + NSAMP;                // [128]
    int* sOut = sBot + NSAMP;                // [128]

    const int tid = threadIdx.x;

    if (tid < NSAMP) {
        int S = blockIdx.x * NSAMP + tid;
        int b = S / 65;
        int r = S - b * 65;
        int itop, jbot, oaddr;
        if (r == 64)      { itop = h[b];           jbot = t[b];           oaddr = b; }
        else if (r < 32)  { itop = h[b];           jbot = ns[b * 64 + r]; oaddr = B_DIM + b * 64 + r; }
        else              { itop = ns[b * 64 + r]; jbot = t[b];           oaddr = B_DIM + b * 64 + r; }
        sTop[tid] = itop; sBot[tid] = jbot; sOut[tid] = oaddr;
    }
#pragma unroll
    for (int i = tid; i < 2048; i += 256)
        ((float4*)W2s)[i] = ((const float4*)W2)[i];
    if (tid < 128) b1s[tid] = b1[tid];
    if (tid < 64) { b2s[tid] = b2[tid]; W3s[tid] = W3[tid]; }
    __syncthreads();

    {
        const int lane = tid & 31;
        const int wid = tid >> 5;
        float4 vb1 = *(const float4*)&b1s[lane << 2];
#pragma unroll
        for (int it = 0; it < NSAMP / 8; it++) {
            int s = it * 8 + wid;
            int i = sTop[s], j = sBot[s];
            float4 pa = *(const float4*)&g_Ptop[i * H1_DIM + (lane << 2)];
            float4 pb = *(const float4*)&g_Pbot[j * H1_DIM + (lane << 2)];
            float4 x;
            x.x = fmaxf(pa.x + pb.x + vb1.x, 0.f);
            x.y = fmaxf(pa.y + pb.y + vb1.y, 0.f);
            x.z = fmaxf(pa.z + pb.z + vb1.z, 0.f);
            x.w = fmaxf(pa.w + pb.w + vb1.w, 0.f);
            *(float4*)&X1[s * X1_STRIDE + (lane << 2)] = x;
        }
    }
    __syncthreads();

    const int tx = tid & 15;
    const int ty = tid >> 4;

    ull acc[8][2];
#pragma unroll
    for (int i = 0; i < 8; i++) { acc[i][0] = 0ull; acc[i][1] = 0ull; }

#pragma unroll 2
    for (int kq = 0; kq < 32; kq++) {
        float4 xa[8];
#pragma unroll
        for (int si = 0; si < 8; si++)
            xa[si] = *(const float4*)&X1[(8 * ty + si) * X1_STRIDE + (kq << 2)];
#pragma unroll
        for (int kk = 0; kk < 4; kk++) {
            const ulonglong2 w =
                *(const ulonglong2*)&W2s[((kq << 2) + kk) * H2_DIM + (tx << 2)];
#pragma unroll
            for (int si = 0; si < 8; si++) {
                float x = (kk == 0) ? xa[si].x : (kk == 1) ? xa[si].y
                        : (kk == 2) ? xa[si].z : xa[si].w;
                ull xp = pack2s(x);
                ffma2(acc[si][0], xp, w.x);
                ffma2(acc[si][1], xp, w.y);
            }
        }
    }

    float4 b2r = *(const float4*)&b2s[tx << 2];
    float4 w3r = *(const float4*)&W3s[tx << 2];
    const float b3v = b3[0];

#pragma unroll
    for (int si = 0; si < 8; si++) {
        float2 c01 = unpk(acc[si][0]);
        float2 c23 = unpk(acc[si][1]);
        float p = 0.f, v;
        v = fmaxf(c01.x + b2r.x, 0.f); p = fmaf(v, w3r.x, p);
        v = fmaxf(c01.y + b2r.y, 0.f); p = fmaf(v, w3r.y, p);
        v = fmaxf(c23.x + b2r.z, 0.f); p = fmaf(v, w3r.z, p);
        v = fmaxf(c23.y + b2r.w, 0.f); p = fmaf(v, w3r.w, p);
#pragma unroll
        for (int m = 8; m > 0; m >>= 1)
            p += __shfl_xor_sync(0xffffffffu, p, m, 16);
        if (tx == 0)
            out[sOut[8 * ty + si]] = p + b3v;
    }
}

// ---------------------------------------------------------------------------
extern "C" void kernel_launch(void* const* d_in, const int* in_sizes, int n_in,
                              void* d_out, int out_size) {
    const float* embed = (const float*)d_in[0];
    const float* W1    = (const float*)d_in[1];
    const float* b1    = (const float*)d_in[2];
    const float* W2    = (const float*)d_in[3];
    const float* b2    = (const float*)d_in[4];
    const float* W3    = (const float*)d_in[5];
    const float* b3    = (const float*)d_in[6];
    const int*   h     = (const int*)d_in[7];
    const int*   t     = (const int*)d_in[8];
    const int*   ns    = (const int*)d_in[9];
    float* out = (float*)d_out;

    convert_w1_kernel<<<H1_DIM, 256>>>(W1);

    cudaFuncSetAttribute(gemm1_mma_kernel, cudaFuncAttributeMaxDynamicSharedMemorySize,
                         G1_SMEM);
    gemm1_mma_kernel<<<NBOT_TC + NTOP_TC, 256, G1_SMEM>>>(embed);

    cudaFuncSetAttribute(mlp2_kernel, cudaFuncAttributeMaxDynamicSharedMemorySize,
                         SMEM2_BYTES);
    mlp2_kernel<<<(B_DIM * 65) / NSAMP, 256, SMEM2_BYTES>>>(h, t, ns, b1, W2, b2, W3, b3, out);
}